// round 12
// baseline (speedup 1.0000x reference)
#include <cuda_runtime.h>
#include <cuda_bf16.h>
#include <cstdint>

#define NFIELDS 26
#define VOCAB   100000
#define BSZ     16384
#define DDIM    64
#define BM1_    128
#define NFEATS  27
#define NINTER  351
#define TOPIN   415
#define KP      448        // padded K for top GEMM (14 x 32)

// ---- device scratch (no allocs allowed) ----
__device__ __nv_bfloat16 g_Xh[BSZ * KP];       // X hi  [B][448]
__device__ __nv_bfloat16 g_Xl[BSZ * KP];       // X lo
__device__ __nv_bfloat16 g_Wh[256 * KP];       // Wt1^T hi [n][448]
__device__ __nv_bfloat16 g_Wl[256 * KP];       // Wt1^T lo

__device__ __forceinline__ void split_store(__nv_bfloat16* ph, __nv_bfloat16* pl,
                                            int off, float x) {
    __nv_bfloat16 h = __float2bfloat16(x);
    float r = x - __bfloat162float(h);
    ph[off] = h;
    pl[off] = __float2bfloat16(r);
}

__device__ __forceinline__ uint32_t smem_u32(const void* p) {
    uint32_t a;
    asm("{ .reg .u64 t; cvta.to.shared.u64 t, %1; cvt.u32.u64 %0, t; }" : "=r"(a) : "l"(p));
    return a;
}

__device__ __forceinline__ void ldsm4(uint32_t* r, uint32_t addr) {
    asm volatile("ldmatrix.sync.aligned.m8n8.x4.shared.b16 {%0,%1,%2,%3}, [%4];"
                 : "=r"(r[0]), "=r"(r[1]), "=r"(r[2]), "=r"(r[3]) : "r"(addr));
}

__device__ __forceinline__ void mma16816(float* c, const uint32_t* a, const uint32_t* b) {
    asm volatile("mma.sync.aligned.m16n8k16.row.col.f32.bf16.bf16.f32 "
                 "{%0,%1,%2,%3}, {%4,%5,%6,%7}, {%8,%9}, {%0,%1,%2,%3};"
                 : "+f"(c[0]), "+f"(c[1]), "+f"(c[2]), "+f"(c[3])
                 : "r"(a[0]), "r"(a[1]), "r"(a[2]), "r"(a[3]), "r"(b[0]), "r"(b[1]));
}

__device__ __forceinline__ void cp16(uint32_t smem_addr, const void* gptr) {
    asm volatile("cp.async.cg.shared.global [%0], [%1], 16;"
                 :: "r"(smem_addr), "l"(gptr));
}

__device__ __forceinline__ uint32_t bf2_hi(float a, float b) {
    __nv_bfloat162 h = __floats2bfloat162_rn(a, b);
    return *reinterpret_cast<uint32_t*>(&h);
}

// ---------------------------------------------------------------------------
// Kernel A: 512 threads, 16 samples/CTA (grid 1024).
//   [blocks 0..111: embedded 32x32 Wt1 transpose/split -> g_Wh/g_Wl]
//   per-CTA uv fold (global W1); per-warp gather -> bf16 hi/lo tiles ->
//   gram via mma.sync -> inline triu extract -> staging; MLP; coalesced flush.
// smem (160768 B):
//   [0,131072)        per-warp 8KB tile regions (fh|fl; reused as C f32)
//   [131072,145408)   xh bf16 [16][448]
//   [145408,159744)   xl bf16 [16][448]
//   [159744,160768)   uv f32 [256]
// ---------------------------------------------------------------------------
#define F_XH  131072
#define F_XL  145408
#define F_UV  159744
#define F_TOT 160768

__global__ __launch_bounds__(512) void dlrm_feats(
    const int*   __restrict__ xcat,
    const float* __restrict__ price,
    const float* __restrict__ emb,
    const float* __restrict__ Wp,
    const float* __restrict__ bp,
    const float* __restrict__ W1,
    const float* __restrict__ b1,
    const float* __restrict__ W2,
    const float* __restrict__ b2,
    const float* __restrict__ Wt1) {
    extern __shared__ char dyn[];
    const int tid  = threadIdx.x;
    const int w    = tid >> 5;
    const int lane = tid & 31;
    const int s    = blockIdx.x * 16 + w;
    const int g    = lane >> 3;
    const int r8   = lane & 7;

    // ---- phase 0: embedded Wt1 transpose/split (blocks 0..111, tid<256) ----
    if (blockIdx.x < 112) {
        if (tid < 256) {
            float* tile = reinterpret_cast<float*>(dyn);   // [32][33]
            const int b  = blockIdx.x;
            const int kt = b % 14, nt = b / 14;
            const int k0 = kt * 32, n0 = nt * 32;
            const int tx = tid & 31, ty = tid >> 5;        // 32 x 8
            #pragma unroll
            for (int i = 0; i < 4; i++) {
                int k = k0 + ty + i * 8;
                tile[(ty + i * 8) * 33 + tx] = (k < TOPIN) ? __ldg(&Wt1[k * 256 + n0 + tx]) : 0.f;
            }
            __syncwarp();
        }
        __syncthreads();
        if (tid < 256) {
            float* tile = reinterpret_cast<float*>(dyn);
            const int b  = blockIdx.x;
            const int kt = b % 14, nt = b / 14;
            const int k0 = kt * 32, n0 = nt * 32;
            const int tx = tid & 31, ty = tid >> 5;
            #pragma unroll
            for (int i = 0; i < 4; i++) {
                int n = n0 + ty + i * 8;
                split_store(g_Wh, g_Wl, n * KP + k0 + tx, tile[tx * 33 + ty + i * 8]);
            }
        }
        __syncthreads();
    }

    // ---- phase 1: uv fold straight from global W1 (coalesced) ----
    if (tid < BM1_) {
        float u = 0.f, v = 0.f;
        #pragma unroll
        for (int d = 0; d < DDIM; d++) {
            float ww = __ldg(&W1[d * BM1_ + tid]);
            u = fmaf(__ldg(&Wp[d]), ww, u);
            v = fmaf(__ldg(&bp[d]), ww, v);
        }
        float* uv = reinterpret_cast<float*>(dyn + F_UV);
        uv[tid]        = u;
        uv[BM1_ + tid] = v + __ldg(&b1[tid]);
    }
    __syncthreads();   // uv ready; tile region free

    char* tb = dyn + w * 8192;
    const uint32_t fhB = smem_u32(tb);
    const uint32_t flB = fhB + 4096;
    __nv_bfloat16* xh = reinterpret_cast<__nv_bfloat16*>(dyn + F_XH) + w * KP;
    __nv_bfloat16* xl = reinterpret_cast<__nv_bfloat16*>(dyn + F_XL) + w * KP;

    const float p = __ldg(&price[s]);

    // ---- phase 2: gather -> bf16 hi/lo swizzled tiles ----
    const int sub = lane >> 4;
    const int q   = lane & 15;
    const int cI  = q >> 1, hI = q & 1;
    #pragma unroll 13
    for (int it = 0; it < 13; it++) {
        int f = 2 * it + sub;
        int idx = __ldg(&xcat[f * BSZ + s]);
        const float4* src = reinterpret_cast<const float4*>(
            emb + ((long long)f * VOCAB + idx) * DDIM);
        float4 v = __ldg(&src[q]);
        __nv_bfloat16 hx = __float2bfloat16(v.x), hy = __float2bfloat16(v.y);
        __nv_bfloat16 hz = __float2bfloat16(v.z), hw = __float2bfloat16(v.w);
        uint2 hi, lo;
        hi.x = bf2_hi(__bfloat162float(hx), __bfloat162float(hy));
        hi.y = bf2_hi(__bfloat162float(hz), __bfloat162float(hw));
        lo.x = bf2_hi(v.x - __bfloat162float(hx), v.y - __bfloat162float(hy));
        lo.y = bf2_hi(v.z - __bfloat162float(hz), v.w - __bfloat162float(hw));
        uint32_t dst = (uint32_t)(f * 128 + ((cI * 16) ^ ((f & 7) * 16)) + hI * 8);
        *reinterpret_cast<uint2*>(tb + dst)        = hi;
        *reinterpret_cast<uint2*>(tb + 4096 + dst) = lo;
    }
    // dense row 26, zero rows 27..31
    {
        #pragma unroll
        for (int half = 0; half < 2; half++) {
            int d = lane + half * 32;
            float de = fmaf(p, __ldg(&Wp[d]), __ldg(&bp[d]));
            __nv_bfloat16 h = __float2bfloat16(de);
            float r = de - __bfloat162float(h);
            int c = d >> 3;
            uint32_t dst = (uint32_t)(26 * 128 + ((c * 16) ^ 32) + (d & 7) * 2);
            *reinterpret_cast<__nv_bfloat16*>(tb + dst)        = h;
            *reinterpret_cast<__nv_bfloat16*>(tb + 4096 + dst) = __float2bfloat16(r);
        }
        for (int t = lane; t < 40; t += 32) {
            int row = 27 + (t >> 3), c = t & 7;
            uint32_t dst = (uint32_t)(row * 128 + ((c * 16) ^ ((row & 7) * 16)));
            *reinterpret_cast<uint4*>(tb + dst)        = make_uint4(0, 0, 0, 0);
            *reinterpret_cast<uint4*>(tb + 4096 + dst) = make_uint4(0, 0, 0, 0);
        }
    }
    // zero pad staging cols 415..447
    {
        __nv_bfloat16 z = __float2bfloat16(0.f);
        int pc = TOPIN + lane;
        if (pc < KP) { xh[pc] = z; xl[pc] = z; }
        if (lane == 0) { xh[447] = z; xl[447] = z; }
    }
    __syncwarp();

    // ---- phase 3: gram via mma.sync: C[32x32] = F F^T (hh + hl + lh) ----
    {
        const uint32_t xorc = r8 * 16;
        const uint32_t aSel = (g >> 1) * 16;
        const uint32_t bSel = (g & 1) * 16;
        uint32_t aRow[2], bRow[2];
        #pragma unroll
        for (int mt = 0; mt < 2; mt++)
            aRow[mt] = (uint32_t)(mt * 16 + (g & 1) * 8 + r8) * 128;
        #pragma unroll
        for (int nt = 0; nt < 2; nt++)
            bRow[nt] = (uint32_t)(nt * 16 + (g >> 1) * 8 + r8) * 128;

        float acc[2][4][4];
        #pragma unroll
        for (int mt = 0; mt < 2; mt++)
            #pragma unroll
            for (int nb = 0; nb < 4; nb++)
                #pragma unroll
                for (int i = 0; i < 4; i++) acc[mt][nb][i] = 0.f;

        #pragma unroll
        for (int kk = 0; kk < 4; kk++) {
            const uint32_t offA = (uint32_t)((kk * 32 + aSel) ^ xorc);
            const uint32_t offB = (uint32_t)((kk * 32 + bSel) ^ xorc);
            uint32_t ah[2][4], al[2][4];
            #pragma unroll
            for (int mt = 0; mt < 2; mt++) {
                ldsm4(ah[mt], fhB + aRow[mt] + offA);
                ldsm4(al[mt], flB + aRow[mt] + offA);
            }
            #pragma unroll
            for (int nt = 0; nt < 2; nt++) {
                uint32_t bh[4], bl[4];
                ldsm4(bh, fhB + bRow[nt] + offB);
                ldsm4(bl, flB + bRow[nt] + offB);
                #pragma unroll
                for (int mt = 0; mt < 2; mt++) {
                    mma16816(acc[mt][2 * nt],     ah[mt], bh);
                    mma16816(acc[mt][2 * nt],     ah[mt], bl);
                    mma16816(acc[mt][2 * nt],     al[mt], bh);
                    mma16816(acc[mt][2 * nt + 1], ah[mt], bh + 2);
                    mma16816(acc[mt][2 * nt + 1], ah[mt], bl + 2);
                    mma16816(acc[mt][2 * nt + 1], al[mt], bh + 2);
                }
            }
        }
        __syncwarp();
        float* Cw = reinterpret_cast<float*>(tb);   // [32][33]
        #pragma unroll
        for (int mt = 0; mt < 2; mt++)
            #pragma unroll
            for (int nb = 0; nb < 4; nb++) {
                int row = mt * 16 + (lane >> 2);
                int col = nb * 8 + (lane & 3) * 2;
                Cw[row * 33 + col]           = acc[mt][nb][0];
                Cw[row * 33 + col + 1]       = acc[mt][nb][1];
                Cw[(row + 8) * 33 + col]     = acc[mt][nb][2];
                Cw[(row + 8) * 33 + col + 1] = acc[mt][nb][3];
            }
        __syncwarp();
        // inline triu extraction (monotone index walk)
        int i = 0, base = 0;
        for (int t = lane; t < NINTER; t += 32) {
            while (t >= base + NFIELDS - i) { base += NFIELDS - i; i++; }
            int jj = i + 1 + (t - base);
            split_store(xh, xl, t, Cw[i * 33 + jj]);
        }
    }

    // ---- phase 4: bottom MLP (uv smem, W2 via L2) ----
    {
        const float* uv = reinterpret_cast<const float*>(dyn + F_UV);
        float a0 = 0.f, a1 = 0.f;
        #pragma unroll 8
        for (int k = 0; k < BM1_; k++) {
            float hk = fmaxf(fmaf(p, uv[k], uv[BM1_ + k]), 0.f);
            float2 w2 = __ldg(reinterpret_cast<const float2*>(W2 + k * 64 + 2 * lane));
            a0 = fmaf(hk, w2.x, a0);
            a1 = fmaf(hk, w2.y, a1);
        }
        float2 b2v = __ldg(reinterpret_cast<const float2*>(b2 + 2 * lane));
        split_store(xh, xl, NINTER + 2 * lane,     fmaxf(a0 + b2v.x, 0.f));
        split_store(xh, xl, NINTER + 2 * lane + 1, fmaxf(a1 + b2v.y, 0.f));
    }
    __syncwarp();

    // ---- phase 5: coalesced flush ----
    {
        const size_t xbase = (size_t)s * KP;
        const uint4* sh = reinterpret_cast<const uint4*>(xh);
        const uint4* sl = reinterpret_cast<const uint4*>(xl);
        uint4* dh = reinterpret_cast<uint4*>(g_Xh + xbase);
        uint4* dl = reinterpret_cast<uint4*>(g_Xl + xbase);
        #pragma unroll
        for (int i = lane; i < 56; i += 32) {
            dh[i] = sh[i];
            dl[i] = sl[i];
        }
    }
}

// ---------------------------------------------------------------------------
// Kernel B: 512 threads / 16 warps, warp tile 16x128 (64 accum regs, no spill).
//   BM=128 (128 CTAs), N=256, K=448 in 7 chunks of 64, 3 split terms.
//   cp.async double-buffered.
// ---------------------------------------------------------------------------
#define SA_HI 0
#define SA_LO 16384
#define SB_HI 32768
#define SB_LO 65536
#define STAGE 98304
#define S_B1  (2 * STAGE)
#define S_W2  (S_B1 + 1024)
#define S_TOT (S_W2 + 1024)

__global__ __launch_bounds__(512, 1) void dlrm_top_mma(
    const float* __restrict__ bt1,
    const float* __restrict__ wt2,
    const float* __restrict__ bt2,
    float* __restrict__ out) {
    extern __shared__ char smem[];
    const uint32_t sb = smem_u32(smem);
    const int tid  = threadIdx.x;
    const int wid  = tid >> 5;
    const int lane = tid & 31;
    const int s0   = blockIdx.x * 128;
    const int wr   = wid & 7;      // row group (16 rows)
    const int wc   = wid >> 3;     // col group (128 cols)
    const int g    = lane >> 3;
    const int r8   = lane & 7;

    if (tid < 256) {
        *reinterpret_cast<float*>(smem + S_B1 + tid * 4) = bt1[tid];
        *reinterpret_cast<float*>(smem + S_W2 + tid * 4) = wt2[tid];
    }

    // load addressing: A 1024 quads (2/thread), B 2048 quads (4/thread)
    int arow[2], aq[2], brow[4], bq[4];
    uint32_t adst[2], bdst[4];
    #pragma unroll
    for (int j = 0; j < 2; j++) {
        int qid = j * 512 + tid;
        arow[j] = qid >> 3; aq[j] = qid & 7;
        adst[j] = (uint32_t)(arow[j] * 128 + ((aq[j] * 16) ^ ((arow[j] & 7) * 16)));
    }
    #pragma unroll
    for (int j = 0; j < 4; j++) {
        int qid = j * 512 + tid;
        brow[j] = qid >> 3; bq[j] = qid & 7;
        bdst[j] = (uint32_t)(brow[j] * 128 + ((bq[j] * 16) ^ ((brow[j] & 7) * 16)));
    }

    const uint32_t xorc = r8 * 16;
    const uint32_t aSel = (g >> 1) * 16;
    const uint32_t bSel = (g & 1) * 16;
    const uint32_t aOff = (uint32_t)(wr * 16 + (g & 1) * 8 + r8) * 128;
    const uint32_t nOff = (uint32_t)(wc * 128 + (g >> 1) * 8 + r8) * 128;

    float acc[16][4];
    #pragma unroll
    for (int nt = 0; nt < 16; nt++)
        #pragma unroll
        for (int i = 0; i < 4; i++) acc[nt][i] = 0.f;

    auto load_chunk = [&](int c, int st) {
        const uint32_t base = sb + st * STAGE;
        #pragma unroll
        for (int j = 0; j < 2; j++) {
            const __nv_bfloat16* sh = g_Xh + (size_t)(s0 + arow[j]) * KP + c * 64 + aq[j] * 8;
            const __nv_bfloat16* sl = g_Xl + (size_t)(s0 + arow[j]) * KP + c * 64 + aq[j] * 8;
            cp16(base + SA_HI + adst[j], sh);
            cp16(base + SA_LO + adst[j], sl);
        }
        #pragma unroll
        for (int j = 0; j < 4; j++) {
            const __nv_bfloat16* sh = g_Wh + (size_t)brow[j] * KP + c * 64 + bq[j] * 8;
            const __nv_bfloat16* sl = g_Wl + (size_t)brow[j] * KP + c * 64 + bq[j] * 8;
            cp16(base + SB_HI + bdst[j], sh);
            cp16(base + SB_LO + bdst[j], sl);
        }
        asm volatile("cp.async.commit_group;" ::: "memory");
    };

    load_chunk(0, 0);

    for (int c = 0; c < 7; c++) {
        if (c < 6) {
            load_chunk(c + 1, (c + 1) & 1);
            asm volatile("cp.async.wait_group 1;" ::: "memory");
        } else {
            asm volatile("cp.async.wait_group 0;" ::: "memory");
        }
        __syncthreads();

        const uint32_t st = sb + (c & 1) * STAGE;
        #pragma unroll
        for (int kl = 0; kl < 4; kl++) {
            uint32_t ah[4], al[4];
            const uint32_t offA = (uint32_t)((kl * 32 + aSel) ^ xorc);
            ldsm4(ah, st + SA_HI + aOff + offA);
            ldsm4(al, st + SA_LO + aOff + offA);
            const uint32_t offB = (uint32_t)((kl * 32 + bSel) ^ xorc);
            #pragma unroll
            for (int pp = 0; pp < 8; pp++) {
                uint32_t bh[4], bl[4];
                uint32_t bb = nOff + (uint32_t)pp * 2048;
                ldsm4(bh, st + SB_HI + bb + offB);
                ldsm4(bl, st + SB_LO + bb + offB);
                mma16816(acc[2 * pp],     ah, bh);
                mma16816(acc[2 * pp],     ah, bl);
                mma16816(acc[2 * pp],     al, bh);
                mma16816(acc[2 * pp + 1], ah, bh + 2);
                mma16816(acc[2 * pp + 1], ah, bl + 2);
                mma16816(acc[2 * pp + 1], al, bh + 2);
            }
        }
        __syncthreads();
    }

    // ---- epilogue: relu+bias, dot wt2, reduce ----
    const float* sb1 = reinterpret_cast<const float*>(smem + S_B1);
    const float* sw2 = reinterpret_cast<const float*>(smem + S_W2);
    float part[2] = {0.f, 0.f};
    #pragma unroll
    for (int nt = 0; nt < 16; nt++) {
        int n0 = wc * 128 + nt * 8 + (lane & 3) * 2;
        float b0v = sb1[n0], b1v = sb1[n0 + 1];
        float w0 = sw2[n0], w1 = sw2[n0 + 1];
        part[0] = fmaf(fmaxf(acc[nt][0] + b0v, 0.f), w0, part[0]);
        part[0] = fmaf(fmaxf(acc[nt][1] + b1v, 0.f), w1, part[0]);
        part[1] = fmaf(fmaxf(acc[nt][2] + b0v, 0.f), w0, part[1]);
        part[1] = fmaf(fmaxf(acc[nt][3] + b1v, 0.f), w1, part[1]);
    }
    #pragma unroll
    for (int hf = 0; hf < 2; hf++) {
        part[hf] += __shfl_xor_sync(0xffffffffu, part[hf], 1);
        part[hf] += __shfl_xor_sync(0xffffffffu, part[hf], 2);
    }

    __syncthreads();
    float* pp = reinterpret_cast<float*>(smem);   // [128][2]
    if ((lane & 3) == 0) {
        #pragma unroll
        for (int hf = 0; hf < 2; hf++) {
            int row = wr * 16 + hf * 8 + (lane >> 2);
            pp[row * 2 + wc] = part[hf];
        }
    }
    __syncthreads();
    if (tid < 128)
        out[s0 + tid] = pp[tid * 2] + pp[tid * 2 + 1] + __ldg(&bt2[0]);
}

// ---------------------------------------------------------------------------
extern "C" void kernel_launch(void* const* d_in, const int* in_sizes, int n_in,
                              void* d_out, int out_size) {
    const int*   xcat  = (const int*)  d_in[0];
    const float* price = (const float*)d_in[1];
    const float* emb   = (const float*)d_in[2];
    const float* Wp    = (const float*)d_in[3];
    const float* bp    = (const float*)d_in[4];
    const float* W1    = (const float*)d_in[5];
    const float* b1    = (const float*)d_in[6];
    const float* W2    = (const float*)d_in[7];
    const float* b2    = (const float*)d_in[8];
    const float* Wt1   = (const float*)d_in[9];
    const float* bt1   = (const float*)d_in[10];
    const float* Wt2   = (const float*)d_in[11];
    const float* bt2   = (const float*)d_in[12];
    float* out = (float*)d_out;

    cudaFuncSetAttribute(dlrm_feats,   cudaFuncAttributeMaxDynamicSharedMemorySize, F_TOT);
    cudaFuncSetAttribute(dlrm_top_mma, cudaFuncAttributeMaxDynamicSharedMemorySize, S_TOT);

    dlrm_feats  <<<BSZ / 16, 512, F_TOT>>>(xcat, price, emb, Wp, bp, W1, b1, W2, b2, Wt1);
    dlrm_top_mma<<<BSZ / 128, 512, S_TOT>>>(bt1, Wt2, bt2, out);
}

// round 15
// speedup vs baseline: 1.0841x; 1.0841x over previous
#include <cuda_runtime.h>
#include <cuda_bf16.h>
#include <cstdint>

#define NFIELDS 26
#define VOCAB   100000
#define BSZ     16384
#define DDIM    64
#define BM1_    128
#define NFEATS  27
#define NINTER  351
#define TOPIN   415
#define KP      448        // padded K for top GEMM (14 x 32)

// ---- device scratch (no allocs allowed) ----
__device__ __nv_bfloat16 g_Xh[BSZ * KP];       // X hi  [B][448]
__device__ __nv_bfloat16 g_Xl[BSZ * KP];       // X lo
__device__ __nv_bfloat16 g_Wh[256 * KP];       // Wt1^T hi [n][448]
__device__ __nv_bfloat16 g_Wl[256 * KP];       // Wt1^T lo

__device__ __forceinline__ void split_store(__nv_bfloat16* ph, __nv_bfloat16* pl,
                                            int off, float x) {
    __nv_bfloat16 h = __float2bfloat16(x);
    float r = x - __bfloat162float(h);
    ph[off] = h;
    pl[off] = __float2bfloat16(r);
}

__device__ __forceinline__ uint32_t smem_u32(const void* p) {
    uint32_t a;
    asm("{ .reg .u64 t; cvta.to.shared.u64 t, %1; cvt.u32.u64 %0, t; }" : "=r"(a) : "l"(p));
    return a;
}

__device__ __forceinline__ void ldsm4(uint32_t* r, uint32_t addr) {
    asm volatile("ldmatrix.sync.aligned.m8n8.x4.shared.b16 {%0,%1,%2,%3}, [%4];"
                 : "=r"(r[0]), "=r"(r[1]), "=r"(r[2]), "=r"(r[3]) : "r"(addr));
}

__device__ __forceinline__ void mma16816(float* c, const uint32_t* a, const uint32_t* b) {
    asm volatile("mma.sync.aligned.m16n8k16.row.col.f32.bf16.bf16.f32 "
                 "{%0,%1,%2,%3}, {%4,%5,%6,%7}, {%8,%9}, {%0,%1,%2,%3};"
                 : "+f"(c[0]), "+f"(c[1]), "+f"(c[2]), "+f"(c[3])
                 : "r"(a[0]), "r"(a[1]), "r"(a[2]), "r"(a[3]), "r"(b[0]), "r"(b[1]));
}

__device__ __forceinline__ void cp16(uint32_t smem_addr, const void* gptr) {
    asm volatile("cp.async.cg.shared.global [%0], [%1], 16;"
                 :: "r"(smem_addr), "l"(gptr));
}

__device__ __forceinline__ uint32_t bf2_hi(float a, float b) {
    __nv_bfloat162 h = __floats2bfloat162_rn(a, b);
    return *reinterpret_cast<uint32_t*>(&h);
}

// ---------------------------------------------------------------------------
// Kernel A (R11 config: 256 threads, 8 samples/CTA, grid 2048, 113KB smem,
//           2 CTAs/SM): embedded Wt1 prep; W1/W2 staging; gram via mma.sync.
// ---------------------------------------------------------------------------
#define F_TB  0
#define F_XH  65536
#define F_XL  72704
#define F_W2  79872
#define F_UV  112640
#define F_TOT 113664

__global__ __launch_bounds__(256) void dlrm_feats(
    const int*   __restrict__ xcat,
    const float* __restrict__ price,
    const float* __restrict__ emb,
    const float* __restrict__ Wp,
    const float* __restrict__ bp,
    const float* __restrict__ W1,
    const float* __restrict__ b1,
    const float* __restrict__ W2,
    const float* __restrict__ b2,
    const float* __restrict__ Wt1) {
    extern __shared__ char dyn[];
    const int tid  = threadIdx.x;
    const int w    = tid >> 5;
    const int lane = tid & 31;
    const int s    = blockIdx.x * 8 + w;
    const int g    = lane >> 3;
    const int r8   = lane & 7;

    // ---- phase 0: embedded Wt1 transpose/split (blocks 0..111 only) ----
    if (blockIdx.x < 112) {
        float* tile = reinterpret_cast<float*>(dyn);   // [32][33]
        const int b  = blockIdx.x;
        const int kt = b % 14, nt = b / 14;
        const int k0 = kt * 32, n0 = nt * 32;
        const int tx = tid & 31, ty = tid >> 5;        // 32 x 8
        #pragma unroll
        for (int i = 0; i < 4; i++) {
            int k = k0 + ty + i * 8;
            tile[(ty + i * 8) * 33 + tx] = (k < TOPIN) ? __ldg(&Wt1[k * 256 + n0 + tx]) : 0.f;
        }
        __syncthreads();
        #pragma unroll
        for (int i = 0; i < 4; i++) {
            int n = n0 + ty + i * 8;
            split_store(g_Wh, g_Wl, n * KP + k0 + tx, tile[tx * 33 + ty + i * 8]);
        }
        __syncthreads();
    }

    // ---- phase 1: stage W1 (into tile region) + W2; fold uv ----
    {
        float4* w2d = reinterpret_cast<float4*>(dyn + F_W2);
        const float4* w2s = reinterpret_cast<const float4*>(W2);
        float4* w1d = reinterpret_cast<float4*>(dyn);
        const float4* w1s = reinterpret_cast<const float4*>(W1);
        #pragma unroll 8
        for (int i = tid; i < 2048; i += 256) {
            w2d[i] = __ldg(&w2s[i]);
            w1d[i] = __ldg(&w1s[i]);
        }
        __syncthreads();
        if (tid < BM1_) {
            const float* w1f = reinterpret_cast<const float*>(dyn);
            float u = 0.f, v = 0.f;
            #pragma unroll
            for (int d = 0; d < DDIM; d++) {
                float ww = w1f[d * BM1_ + tid];
                u = fmaf(__ldg(&Wp[d]), ww, u);
                v = fmaf(__ldg(&bp[d]), ww, v);
            }
            float* uv = reinterpret_cast<float*>(dyn + F_UV);
            uv[tid]        = u;
            uv[BM1_ + tid] = v + __ldg(&b1[tid]);
        }
        __syncthreads();   // uv ready; tile region free for gather
    }

    char* tb = dyn + w * 8192;
    const uint32_t fhB = smem_u32(tb);
    const uint32_t flB = fhB + 4096;
    __nv_bfloat16* xh = reinterpret_cast<__nv_bfloat16*>(dyn + F_XH) + w * KP;
    __nv_bfloat16* xl = reinterpret_cast<__nv_bfloat16*>(dyn + F_XL) + w * KP;

    const float p = __ldg(&price[s]);

    // ---- phase 2: gather -> bf16 hi/lo swizzled tiles ----
    const int sub = lane >> 4;
    const int q   = lane & 15;
    const int cI  = q >> 1, hI = q & 1;
    #pragma unroll 13
    for (int it = 0; it < 13; it++) {
        int f = 2 * it + sub;
        int idx = __ldg(&xcat[f * BSZ + s]);
        const float4* src = reinterpret_cast<const float4*>(
            emb + ((long long)f * VOCAB + idx) * DDIM);
        float4 v = __ldg(&src[q]);
        __nv_bfloat16 hx = __float2bfloat16(v.x), hy = __float2bfloat16(v.y);
        __nv_bfloat16 hz = __float2bfloat16(v.z), hw = __float2bfloat16(v.w);
        uint2 hi, lo;
        hi.x = bf2_hi(__bfloat162float(hx), __bfloat162float(hy));
        hi.y = bf2_hi(__bfloat162float(hz), __bfloat162float(hw));
        lo.x = bf2_hi(v.x - __bfloat162float(hx), v.y - __bfloat162float(hy));
        lo.y = bf2_hi(v.z - __bfloat162float(hz), v.w - __bfloat162float(hw));
        uint32_t dst = (uint32_t)(f * 128 + ((cI * 16) ^ ((f & 7) * 16)) + hI * 8);
        *reinterpret_cast<uint2*>(tb + dst)        = hi;
        *reinterpret_cast<uint2*>(tb + 4096 + dst) = lo;
    }
    // dense row 26, zero rows 27..31
    {
        #pragma unroll
        for (int half = 0; half < 2; half++) {
            int d = lane + half * 32;
            float de = fmaf(p, __ldg(&Wp[d]), __ldg(&bp[d]));
            __nv_bfloat16 h = __float2bfloat16(de);
            float r = de - __bfloat162float(h);
            int c = d >> 3;
            uint32_t dst = (uint32_t)(26 * 128 + ((c * 16) ^ 32) + (d & 7) * 2);
            *reinterpret_cast<__nv_bfloat16*>(tb + dst)        = h;
            *reinterpret_cast<__nv_bfloat16*>(tb + 4096 + dst) = __float2bfloat16(r);
        }
        for (int t = lane; t < 40; t += 32) {
            int row = 27 + (t >> 3), c = t & 7;
            uint32_t dst = (uint32_t)(row * 128 + ((c * 16) ^ ((row & 7) * 16)));
            *reinterpret_cast<uint4*>(tb + dst)        = make_uint4(0, 0, 0, 0);
            *reinterpret_cast<uint4*>(tb + 4096 + dst) = make_uint4(0, 0, 0, 0);
        }
    }
    // zero pad staging cols 415..447
    {
        __nv_bfloat16 z = __float2bfloat16(0.f);
        int pc = TOPIN + lane;
        if (pc < KP) { xh[pc] = z; xl[pc] = z; }
        if (lane == 0) { xh[447] = z; xl[447] = z; }
    }
    __syncwarp();

    // ---- phase 3: gram via mma.sync: C[32x32] = F F^T (hh + hl + lh) ----
    {
        const uint32_t xorc = r8 * 16;
        const uint32_t aSel = (g >> 1) * 16;
        const uint32_t bSel = (g & 1) * 16;
        uint32_t aRow[2], bRow[2];
        #pragma unroll
        for (int mt = 0; mt < 2; mt++)
            aRow[mt] = (uint32_t)(mt * 16 + (g & 1) * 8 + r8) * 128;
        #pragma unroll
        for (int nt = 0; nt < 2; nt++)
            bRow[nt] = (uint32_t)(nt * 16 + (g >> 1) * 8 + r8) * 128;

        float acc[2][4][4];
        #pragma unroll
        for (int mt = 0; mt < 2; mt++)
            #pragma unroll
            for (int nb = 0; nb < 4; nb++)
                #pragma unroll
                for (int i = 0; i < 4; i++) acc[mt][nb][i] = 0.f;

        #pragma unroll
        for (int kk = 0; kk < 4; kk++) {
            const uint32_t offA = (uint32_t)((kk * 32 + aSel) ^ xorc);
            const uint32_t offB = (uint32_t)((kk * 32 + bSel) ^ xorc);
            uint32_t ah[2][4], al[2][4];
            #pragma unroll
            for (int mt = 0; mt < 2; mt++) {
                ldsm4(ah[mt], fhB + aRow[mt] + offA);
                ldsm4(al[mt], flB + aRow[mt] + offA);
            }
            #pragma unroll
            for (int nt = 0; nt < 2; nt++) {
                uint32_t bh[4], bl[4];
                ldsm4(bh, fhB + bRow[nt] + offB);
                ldsm4(bl, flB + bRow[nt] + offB);
                #pragma unroll
                for (int mt = 0; mt < 2; mt++) {
                    mma16816(acc[mt][2 * nt],     ah[mt], bh);
                    mma16816(acc[mt][2 * nt],     ah[mt], bl);
                    mma16816(acc[mt][2 * nt],     al[mt], bh);
                    mma16816(acc[mt][2 * nt + 1], ah[mt], bh + 2);
                    mma16816(acc[mt][2 * nt + 1], ah[mt], bl + 2);
                    mma16816(acc[mt][2 * nt + 1], al[mt], bh + 2);
                }
            }
        }
        __syncwarp();
        float* Cw = reinterpret_cast<float*>(tb);   // [32][33]
        #pragma unroll
        for (int mt = 0; mt < 2; mt++)
            #pragma unroll
            for (int nb = 0; nb < 4; nb++) {
                int row = mt * 16 + (lane >> 2);
                int col = nb * 8 + (lane & 3) * 2;
                Cw[row * 33 + col]           = acc[mt][nb][0];
                Cw[row * 33 + col + 1]       = acc[mt][nb][1];
                Cw[(row + 8) * 33 + col]     = acc[mt][nb][2];
                Cw[(row + 8) * 33 + col + 1] = acc[mt][nb][3];
            }
        __syncwarp();
        // inline triu extraction (monotone index walk)
        int i = 0, base = 0;
        for (int t = lane; t < NINTER; t += 32) {
            while (t >= base + NFIELDS - i) { base += NFIELDS - i; i++; }
            int jj = i + 1 + (t - base);
            split_store(xh, xl, t, Cw[i * 33 + jj]);
        }
    }

    // ---- phase 4: bottom MLP from smem ----
    {
        const float* uv  = reinterpret_cast<const float*>(dyn + F_UV);
        const float* w2s = reinterpret_cast<const float*>(dyn + F_W2);
        float a0 = 0.f, a1 = 0.f;
        #pragma unroll 8
        for (int k = 0; k < BM1_; k++) {
            float hk = fmaxf(fmaf(p, uv[k], uv[BM1_ + k]), 0.f);
            float2 w2 = *reinterpret_cast<const float2*>(&w2s[k * 64 + 2 * lane]);
            a0 = fmaf(hk, w2.x, a0);
            a1 = fmaf(hk, w2.y, a1);
        }
        float2 b2v = __ldg(reinterpret_cast<const float2*>(b2 + 2 * lane));
        split_store(xh, xl, NINTER + 2 * lane,     fmaxf(a0 + b2v.x, 0.f));
        split_store(xh, xl, NINTER + 2 * lane + 1, fmaxf(a1 + b2v.y, 0.f));
    }
    __syncwarp();

    // ---- phase 5: coalesced flush ----
    {
        const size_t xbase = (size_t)s * KP;
        const uint4* sh = reinterpret_cast<const uint4*>(xh);
        const uint4* sl = reinterpret_cast<const uint4*>(xl);
        uint4* dh = reinterpret_cast<uint4*>(g_Xh + xbase);
        uint4* dl = reinterpret_cast<uint4*>(g_Xl + xbase);
        #pragma unroll
        for (int i = lane; i < 56; i += 32) {
            dh[i] = sh[i];
            dl[i] = sl[i];
        }
    }
}

// ---------------------------------------------------------------------------
// Kernel B: 512 threads / 16 warps, 4x4 warp grid, warp tile 32 rows x 64 cols.
//   acc = 64 regs; ldsm per k16 = 12/warp for 48 MMAs (192/CTA vs 288 before).
//   BM=128 (128 CTAs), N=256, K=448 in 7 chunks of 64, cp.async double-buffer.
// ---------------------------------------------------------------------------
#define SA_HI 0
#define SA_LO 16384
#define SB_HI 32768
#define SB_LO 65536
#define STAGE 98304
#define S_B1  (2 * STAGE)
#define S_W2  (S_B1 + 1024)
#define S_TOT (S_W2 + 1024)

__global__ __launch_bounds__(512, 1) void dlrm_top_mma(
    const float* __restrict__ bt1,
    const float* __restrict__ wt2,
    const float* __restrict__ bt2,
    float* __restrict__ out) {
    extern __shared__ char smem[];
    const uint32_t sb = smem_u32(smem);
    const int tid  = threadIdx.x;
    const int wid  = tid >> 5;
    const int lane = tid & 31;
    const int s0   = blockIdx.x * 128;
    const int wr   = wid & 3;      // row group (32 rows)
    const int wc   = wid >> 2;     // col group (64 cols)
    const int g    = lane >> 3;
    const int r8   = lane & 7;

    if (tid < 256) {
        *reinterpret_cast<float*>(smem + S_B1 + tid * 4) = bt1[tid];
        *reinterpret_cast<float*>(smem + S_W2 + tid * 4) = wt2[tid];
    }

    // load addressing: A 1024 quads (2/thread), B 2048 quads (4/thread)
    int arow[2], aq[2], brow[4], bq[4];
    uint32_t adst[2], bdst[4];
    #pragma unroll
    for (int j = 0; j < 2; j++) {
        int qid = j * 512 + tid;
        arow[j] = qid >> 3; aq[j] = qid & 7;
        adst[j] = (uint32_t)(arow[j] * 128 + ((aq[j] * 16) ^ ((arow[j] & 7) * 16)));
    }
    #pragma unroll
    for (int j = 0; j < 4; j++) {
        int qid = j * 512 + tid;
        brow[j] = qid >> 3; bq[j] = qid & 7;
        bdst[j] = (uint32_t)(brow[j] * 128 + ((bq[j] * 16) ^ ((brow[j] & 7) * 16)));
    }

    const uint32_t xorc = r8 * 16;
    const uint32_t aSel = (g >> 1) * 16;
    const uint32_t bSel = (g & 1) * 16;
    uint32_t aOff[2];
    #pragma unroll
    for (int mt = 0; mt < 2; mt++)
        aOff[mt] = (uint32_t)(wr * 32 + mt * 16 + (g & 1) * 8 + r8) * 128;
    uint32_t bOff[4];
    #pragma unroll
    for (int pq = 0; pq < 4; pq++)
        bOff[pq] = (uint32_t)(wc * 64 + pq * 16 + (g >> 1) * 8 + r8) * 128;

    float acc[2][8][4];
    #pragma unroll
    for (int mt = 0; mt < 2; mt++)
        #pragma unroll
        for (int nt = 0; nt < 8; nt++)
            #pragma unroll
            for (int i = 0; i < 4; i++) acc[mt][nt][i] = 0.f;

    auto load_chunk = [&](int c, int st) {
        const uint32_t base = sb + st * STAGE;
        #pragma unroll
        for (int j = 0; j < 2; j++) {
            const __nv_bfloat16* sh = g_Xh + (size_t)(s0 + arow[j]) * KP + c * 64 + aq[j] * 8;
            const __nv_bfloat16* sl = g_Xl + (size_t)(s0 + arow[j]) * KP + c * 64 + aq[j] * 8;
            cp16(base + SA_HI + adst[j], sh);
            cp16(base + SA_LO + adst[j], sl);
        }
        #pragma unroll
        for (int j = 0; j < 4; j++) {
            const __nv_bfloat16* sh = g_Wh + (size_t)brow[j] * KP + c * 64 + bq[j] * 8;
            const __nv_bfloat16* sl = g_Wl + (size_t)brow[j] * KP + c * 64 + bq[j] * 8;
            cp16(base + SB_HI + bdst[j], sh);
            cp16(base + SB_LO + bdst[j], sl);
        }
        asm volatile("cp.async.commit_group;" ::: "memory");
    };

    load_chunk(0, 0);

    for (int c = 0; c < 7; c++) {
        if (c < 6) {
            load_chunk(c + 1, (c + 1) & 1);
            asm volatile("cp.async.wait_group 1;" ::: "memory");
        } else {
            asm volatile("cp.async.wait_group 0;" ::: "memory");
        }
        __syncthreads();

        const uint32_t st = sb + (c & 1) * STAGE;
        #pragma unroll
        for (int kl = 0; kl < 4; kl++) {
            uint32_t ah[2][4], al[2][4];
            const uint32_t offA = (uint32_t)((kl * 32 + aSel) ^ xorc);
            ldsm4(ah[0], st + SA_HI + aOff[0] + offA);
            ldsm4(ah[1], st + SA_HI + aOff[1] + offA);
            ldsm4(al[0], st + SA_LO + aOff[0] + offA);
            ldsm4(al[1], st + SA_LO + aOff[1] + offA);
            const uint32_t offB = (uint32_t)((kl * 32 + bSel) ^ xorc);
            #pragma unroll
            for (int pq = 0; pq < 4; pq++) {
                uint32_t bh[4], bl[4];
                ldsm4(bh, st + SB_HI + bOff[pq] + offB);
                ldsm4(bl, st + SB_LO + bOff[pq] + offB);
                #pragma unroll
                for (int mt = 0; mt < 2; mt++) {
                    mma16816(acc[mt][2 * pq],     ah[mt], bh);
                    mma16816(acc[mt][2 * pq],     ah[mt], bl);
                    mma16816(acc[mt][2 * pq],     al[mt], bh);
                    mma16816(acc[mt][2 * pq + 1], ah[mt], bh + 2);
                    mma16816(acc[mt][2 * pq + 1], ah[mt], bl + 2);
                    mma16816(acc[mt][2 * pq + 1], al[mt], bh + 2);
                }
            }
        }
        __syncthreads();
    }

    // ---- epilogue: relu+bias, dot wt2, reduce ----
    const float* sb1 = reinterpret_cast<const float*>(smem + S_B1);
    const float* sw2 = reinterpret_cast<const float*>(smem + S_W2);
    float part[2][2] = {{0.f, 0.f}, {0.f, 0.f}};
    #pragma unroll
    for (int nt = 0; nt < 8; nt++) {
        int n0 = wc * 64 + nt * 8 + (lane & 3) * 2;
        float b0v = sb1[n0], b1v = sb1[n0 + 1];
        float w0 = sw2[n0], w1 = sw2[n0 + 1];
        #pragma unroll
        for (int mt = 0; mt < 2; mt++) {
            part[mt][0] = fmaf(fmaxf(acc[mt][nt][0] + b0v, 0.f), w0, part[mt][0]);
            part[mt][0] = fmaf(fmaxf(acc[mt][nt][1] + b1v, 0.f), w1, part[mt][0]);
            part[mt][1] = fmaf(fmaxf(acc[mt][nt][2] + b0v, 0.f), w0, part[mt][1]);
            part[mt][1] = fmaf(fmaxf(acc[mt][nt][3] + b1v, 0.f), w1, part[mt][1]);
        }
    }
    #pragma unroll
    for (int mt = 0; mt < 2; mt++)
        #pragma unroll
        for (int hf = 0; hf < 2; hf++) {
            part[mt][hf] += __shfl_xor_sync(0xffffffffu, part[mt][hf], 1);
            part[mt][hf] += __shfl_xor_sync(0xffffffffu, part[mt][hf], 2);
        }

    __syncthreads();
    float* pp = reinterpret_cast<float*>(smem);   // [128][4]
    if ((lane & 3) == 0) {
        #pragma unroll
        for (int mt = 0; mt < 2; mt++)
            #pragma unroll
            for (int hf = 0; hf < 2; hf++) {
                int row = wr * 32 + mt * 16 + hf * 8 + (lane >> 2);
                pp[row * 4 + wc] = part[mt][hf];
            }
    }
    __syncthreads();
    if (tid < 128)
        out[s0 + tid] = pp[tid * 4] + pp[tid * 4 + 1] + pp[tid * 4 + 2] + pp[tid * 4 + 3]
                      + __ldg(&bt2[0]);
}

// ---------------------------------------------------------------------------
extern "C" void kernel_launch(void* const* d_in, const int* in_sizes, int n_in,
                              void* d_out, int out_size) {
    const int*   xcat  = (const int*)  d_in[0];
    const float* price = (const float*)d_in[1];
    const float* emb   = (const float*)d_in[2];
    const float* Wp    = (const float*)d_in[3];
    const float* bp    = (const float*)d_in[4];
    const float* W1    = (const float*)d_in[5];
    const float* b1    = (const float*)d_in[6];
    const float* W2    = (const float*)d_in[7];
    const float* b2    = (const float*)d_in[8];
    const float* Wt1   = (const float*)d_in[9];
    const float* bt1   = (const float*)d_in[10];
    const float* Wt2   = (const float*)d_in[11];
    const float* bt2   = (const float*)d_in[12];
    float* out = (float*)d_out;

    cudaFuncSetAttribute(dlrm_feats,   cudaFuncAttributeMaxDynamicSharedMemorySize, F_TOT);
    cudaFuncSetAttribute(dlrm_top_mma, cudaFuncAttributeMaxDynamicSharedMemorySize, S_TOT);

    dlrm_feats  <<<BSZ / 8, 256, F_TOT>>>(xcat, price, emb, Wp, bp, W1, b1, W2, b2, Wt1);
    dlrm_top_mma<<<BSZ / 128, 512, S_TOT>>>(bt1, Wt2, bt2, out);
}